// round 1
// baseline (speedup 1.0000x reference)
#include <cuda_runtime.h>

#define BATCH 64
#define IN    1024
#define OUT   1024
#define DM    64
#define HID   256

// scratch (no cudaMalloc allowed)
__device__ float g_Px[32*HID];      // pe_x @ W1[0:64]   + b1
__device__ float g_Py[32*HID];      // pe_y @ W1[64:128]
__device__ float g_Pb[32*HID];      // pe_b @ Wb1[32:96] + bb1
__device__ float g_s [BATCH];       // sum_g x[b,g]
__device__ float g_Q [BATCH*32*HID];// (Px + xchunk@W1[128:160]) * 2*log2(e)
__device__ float g_Hp[BATCH*4*HID]; // partial H
__device__ float g_o0[BATCH*OUT];   // out before bias net

#define TWO_LOG2E 2.8853900817779268f
#define LOG2_10000 13.287712379549449f

__device__ __forceinline__ float ex2a(float x){ float r; asm("ex2.approx.f32 %0, %1;" : "=f"(r) : "f"(x)); return r; }
__device__ __forceinline__ float rcpa(float x){ float r; asm("rcp.approx.f32 %0, %1;" : "=f"(r) : "f"(x)); return r; }
// tanh(z) given t = z * 2*log2(e):  1 - 2/(exp(2z)+1)
__device__ __forceinline__ float tanh_t(float t){ return fmaf(-2.0f, rcpa(ex2a(t) + 1.0f), 1.0f); }

// ---------------------------------------------------------------- K1
// bid<32: Px(+b1), <64: Py, <96: Pb(+bb1), else per-b sum of x
__global__ void k1_precompute(const float* __restrict__ x,
                              const float* __restrict__ W1, const float* __restrict__ b1,
                              const float* __restrict__ Wb1, const float* __restrict__ bb1)
{
    int bid = blockIdx.x;
    int c = threadIdx.x;
    if (bid < 96) {
        int type = bid >> 5;
        int pos  = bid & 31;
        __shared__ float pe[DM];
        if (c < 32) {
            float inv = ex2a(-LOG2_10000 * ((float)c * (1.0f/32.0f)));
            float ang = (float)pos * inv;
            pe[2*c]   = sinf(ang);
            pe[2*c+1] = cosf(ang);
        }
        __syncthreads();
        const float* W;
        float acc;
        if (type == 0)      { W = W1;            acc = b1[c];  }
        else if (type == 1) { W = W1 + 64*HID;   acc = 0.0f;   }
        else                { W = Wb1 + 32*HID;  acc = bb1[c]; }
        #pragma unroll 8
        for (int d = 0; d < DM; ++d) acc = fmaf(pe[d], W[d*HID + c], acc);
        if (type == 0)      g_Px[pos*HID + c] = acc;
        else if (type == 1) g_Py[pos*HID + c] = acc;
        else                g_Pb[pos*HID + c] = acc;
    } else {
        int b = bid - 96;
        __shared__ float red[256];
        float s = 0.0f;
        for (int i = c; i < IN; i += 256) s += x[b*IN + i];
        red[c] = s; __syncthreads();
        for (int off = 128; off > 0; off >>= 1) {
            if (c < off) red[c] += red[c + off];
            __syncthreads();
        }
        if (c == 0) g_s[b] = red[0];
    }
}

// ---------------------------------------------------------------- K2
// Q[b][j][c] = (Px[j][c] + sum_k x[b, j*32+k] * W1[128+k][c]) * 2log2e
__global__ void k2_Q(const float* __restrict__ x, const float* __restrict__ W1)
{
    int bj = blockIdx.x;            // b*32 + j
    int b = bj >> 5, j = bj & 31;
    int c = threadIdx.x;
    __shared__ float xs[32];
    if (c < 32) xs[c] = x[b*IN + j*32 + c];
    __syncthreads();
    float acc = g_Px[j*HID + c];
    const float* Wc = W1 + 128*HID + c;
    #pragma unroll
    for (int k = 0; k < 32; ++k) acc = fmaf(xs[k], Wc[k*HID], acc);
    g_Q[bj*HID + c] = acc * TWO_LOG2E;
}

// ---------------------------------------------------------------- K3
// Hp[b][sp][c] = sum over 8 t's, 32 j's of x[b, t*32+j]*tanh(Q[b][j]+Py[t])
__global__ void k3_main(const float* __restrict__ x)
{
    int bx = blockIdx.x;            // b*4 + sp
    int b = bx >> 2, sp = bx & 3;
    int c = threadIdx.x;
    __shared__ float xs[256];
    xs[c] = x[b*IN + sp*256 + c];
    float qv[32];
    #pragma unroll
    for (int j = 0; j < 32; ++j) qv[j] = g_Q[(b*32 + j)*HID + c];
    __syncthreads();
    float acc0 = 0.0f, acc1 = 0.0f;
    #pragma unroll 1
    for (int tt = 0; tt < 8; ++tt) {
        int t = sp*8 + tt;
        float py = g_Py[t*HID + c] * TWO_LOG2E;
        #pragma unroll
        for (int j = 0; j < 32; j += 2) {
            acc0 = fmaf(xs[tt*32 + j    ], tanh_t(qv[j    ] + py), acc0);
            acc1 = fmaf(xs[tt*32 + j + 1], tanh_t(qv[j + 1] + py), acc1);
        }
    }
    g_Hp[bx*HID + c] = acc0 + acc1;
}

// ---------------------------------------------------------------- K4
// out0[b][o] = H[b] @ W2[:,o] + s_b * b2[o]; 8 b's x 32 o's per CTA
__global__ void k4_out0(const float* __restrict__ W2, const float* __restrict__ b2)
{
    int ot = blockIdx.x & 31;       // o tile (32 cols)
    int bg = blockIdx.x >> 5;       // b group (8 rows), grid = 256
    int t = threadIdx.x;
    __shared__ float Hs[8*HID];     // 8 KB
    __shared__ float W2s[HID*32];   // 32 KB
    for (int i = t; i < 8*HID; i += 256) {
        int bl = i >> 8, c = i & 255;
        float v = 0.0f;
        #pragma unroll
        for (int sp = 0; sp < 4; ++sp) v += g_Hp[((bg*8 + bl)*4 + sp)*HID + c];
        Hs[i] = v;
    }
    for (int i = t; i < HID*32; i += 256) {
        int cc = i >> 5, ol = i & 31;
        W2s[i] = W2[cc*OUT + ot*32 + ol];
    }
    __syncthreads();
    int bl = t >> 5, ol = t & 31;
    float acc = 0.0f;
    #pragma unroll 8
    for (int cc = 0; cc < HID; ++cc)
        acc = fmaf(Hs[bl*HID + cc], W2s[cc*32 + ol], acc);
    int b = bg*8 + bl, o = ot*32 + ol;
    g_o0[b*OUT + o] = acc + g_s[b] * b2[o];
}

// ---------------------------------------------------------------- K5
// bias hypernetwork + final add
__global__ void k5_bias(const float* __restrict__ Wb1, const float* __restrict__ Wb2,
                        const float* __restrict__ bb2, float* __restrict__ out)
{
    int bx = blockIdx.x;            // b*32 + tx
    int b = bx >> 5, tx = bx & 31;
    int c = threadIdx.x;
    __shared__ float oc[32];
    __shared__ float hb[HID];
    __shared__ float pb[8*32];
    if (c < 32) oc[c] = g_o0[b*OUT + tx*32 + c];
    __syncthreads();
    float acc = g_Pb[tx*HID + c];
    const float* Wc = Wb1 + c;
    #pragma unroll
    for (int k = 0; k < 32; ++k) acc = fmaf(oc[k], Wc[k*HID], acc);
    hb[c] = tanh_t(acc * TWO_LOG2E);
    __syncthreads();
    int w = c >> 5, lane = c & 31;
    float part = 0.0f;
    #pragma unroll
    for (int k = 0; k < 32; ++k) {
        int cc = w*32 + k;
        part = fmaf(hb[cc], Wb2[cc*32 + lane], part);
    }
    pb[c] = part;
    __syncthreads();
    if (c < 32) {
        float bias = bb2[c];
        #pragma unroll
        for (int w2 = 0; w2 < 8; ++w2) bias += pb[w2*32 + c];
        out[b*OUT + tx*32 + c] = oc[c] + bias;
    }
}

extern "C" void kernel_launch(void* const* d_in, const int* in_sizes, int n_in,
                              void* d_out, int out_size)
{
    const float* x   = (const float*)d_in[0];
    // d_in[1] = output_size (fixed 1024, unused)
    const float* W1  = (const float*)d_in[2];
    const float* b1  = (const float*)d_in[3];
    const float* W2  = (const float*)d_in[4];
    const float* b2  = (const float*)d_in[5];
    const float* Wb1 = (const float*)d_in[6];
    const float* bb1 = (const float*)d_in[7];
    const float* Wb2 = (const float*)d_in[8];
    const float* bb2 = (const float*)d_in[9];
    float* out = (float*)d_out;

    k1_precompute<<<160, 256>>>(x, W1, b1, Wb1, bb1);
    k2_Q<<<2048, 256>>>(x, W1);
    k3_main<<<256, 256>>>(x);
    k4_out0<<<256, 256>>>(W2, b2);
    k5_bias<<<2048, 256>>>(Wb1, Wb2, bb2, out);
}